// round 6
// baseline (speedup 1.0000x reference)
#include <cuda_runtime.h>
#include <math.h>
#include <stdint.h>

#define N_NODES 16384
#define F_DIM   256
#define EPS_NORM 1e-12f

// ---------------- scratch (allocation-free: __device__ globals) ----------------
__device__ float g_dinv[N_NODES];            // 1/sqrt(deg)
__device__ float g_sfeatT[F_DIM * N_NODES];  // tf32_rn(dinv[k]*feat[k][n]), [n][k] K-major
__device__ float g_agg[N_NODES * F_DIM];     // feat_agg

// ============================ PTX helpers (sm_80+ portable) ==================
__device__ __forceinline__ uint32_t smem_to_u32(const void* p) {
    uint32_t a;
    asm("{ .reg .u64 t; cvta.to.shared.u64 t, %1; cvt.u32.u64 %0, t; }" : "=r"(a) : "l"(p));
    return a;
}

#define LDSM_X4(r0, r1, r2, r3, addr) \
    asm volatile("ldmatrix.sync.aligned.m8n8.x4.shared.b16 {%0,%1,%2,%3}, [%4];" \
        : "=r"(r0), "=r"(r1), "=r"(r2), "=r"(r3) : "r"(addr))

#define MMA_TF32(d, a, b) \
    asm volatile("mma.sync.aligned.m16n8k8.row.col.f32.tf32.tf32.f32 " \
        "{%0,%1,%2,%3}, {%4,%5,%6,%7}, {%8,%9}, {%0,%1,%2,%3};" \
        : "+f"((d)[0]), "+f"((d)[1]), "+f"((d)[2]), "+f"((d)[3]) \
        : "r"((a)[0]), "r"((a)[1]), "r"((a)[2]), "r"((a)[3]), \
          "r"((b)[0]), "r"((b)[1]))

#define CP_ASYNC_16(dst, src) \
    asm volatile("cp.async.cg.shared.global [%0], [%1], 16;" :: "r"(dst), "l"(src))
#define CP_ASYNC_COMMIT() asm volatile("cp.async.commit_group;" ::: "memory")
#define CP_ASYNC_WAIT_1() asm volatile("cp.async.wait_group 1;" ::: "memory")

__device__ __forceinline__ uint32_t tf32_rn_bits(uint32_t b) {
    float f = __uint_as_float(b);
    uint32_t r;
    asm("cvt.rna.tf32.f32 %0, %1;" : "=r"(r) : "f"(f));
    return r;
}

// ---------------- kernel 1: row sums of A (+1 for I), dinv = rsqrt ----------
__global__ void __launch_bounds__(256) rowsum_kernel(const float* __restrict__ A) {
    const int row = blockIdx.x;
    const float4* arow = reinterpret_cast<const float4*>(A + (size_t)row * N_NODES);
    float s = 0.f;
    #pragma unroll 4
    for (int i = threadIdx.x; i < N_NODES / 4; i += 256) {
        float4 v = arow[i];
        s += (v.x + v.y) + (v.z + v.w);
    }
    __shared__ float red[8];
    #pragma unroll
    for (int o = 16; o > 0; o >>= 1) s += __shfl_down_sync(0xffffffffu, s, o);
    if ((threadIdx.x & 31) == 0) red[threadIdx.x >> 5] = s;
    __syncthreads();
    if (threadIdx.x < 32) {
        s = (threadIdx.x < 8) ? red[threadIdx.x] : 0.f;
        #pragma unroll
        for (int o = 4; o > 0; o >>= 1) s += __shfl_down_sync(0xffffffffu, s, o);
        if (threadIdx.x == 0) g_dinv[row] = rsqrtf(s + 1.0f);
    }
}

// ---------------- kernel 2: sfeatT[n][k] = tf32_rn(dinv[k] * feat[k][n]) ----
__global__ void __launch_bounds__(256) transpose_scale_kernel(const float* __restrict__ feat) {
    __shared__ float t[32][33];
    const int k0 = blockIdx.x * 32;
    const int n0 = blockIdx.y * 32;
    const int tx = threadIdx.x, ty = threadIdx.y;
    #pragma unroll
    for (int i = 0; i < 4; i++) {
        int k = k0 + ty + i * 8;
        t[ty + i * 8][tx] = g_dinv[k] * feat[(size_t)k * F_DIM + n0 + tx];
    }
    __syncthreads();
    #pragma unroll
    for (int i = 0; i < 4; i++) {
        int n = n0 + ty + i * 8;
        uint32_t b = tf32_rn_bits(__float_as_uint(t[tx][ty + i * 8]));
        g_sfeatT[(size_t)n * N_NODES + k0 + tx] = __uint_as_float(b);
    }
}

// ---------------- kernel 3: GEMM1 via mma.sync tf32 --------------------------
// C[16384,256] = A @ sfeatT^T ; agg = dinv_i*C + dinv_i^2*feat
// CTA tile 128x128x32, 3-stage cp.async pipeline, 8 warps (2m x 4n), warp 64x32.
// Inner loop: fragment double-buffering across k-steps to hide LDSM latency.
#define G1_BK       32
#define G1_KT       (N_NODES / G1_BK)          /* 512 */
#define G1_ROWB     144                        /* 32 floats + 16B pad */
#define G1_TILEB    (128 * G1_ROWB)            /* 18432 per A or B tile */
#define G1_STAGEB   (2 * G1_TILEB)             /* 36864 */
#define G1_SMEM     (3 * G1_STAGEB)            /* 110592 */

__device__ __forceinline__ void g1_load_stage(uint32_t sbuf, const float* __restrict__ A,
                                              const float* __restrict__ BT,
                                              int m0, int n0, int kt, int tid) {
    const int k0 = kt * G1_BK;
    #pragma unroll
    for (int i = 0; i < 4; i++) {
        int id = tid + i * 256;
        int row = id >> 3, c = id & 7;
        uint32_t dst = sbuf + row * G1_ROWB + c * 16;
        const float* src = A + (size_t)(m0 + row) * N_NODES + k0 + c * 4;
        CP_ASYNC_16(dst, src);
    }
    #pragma unroll
    for (int i = 0; i < 4; i++) {
        int id = tid + i * 256;
        int row = id >> 3, c = id & 7;
        uint32_t dst = sbuf + G1_TILEB + row * G1_ROWB + c * 16;
        const float* src = BT + (size_t)(n0 + row) * N_NODES + k0 + c * 4;
        CP_ASYNC_16(dst, src);
    }
}

__global__ void __launch_bounds__(256, 2) gemm1_mma_kernel(const float* __restrict__ A,
                                                           const float* __restrict__ feat) {
    extern __shared__ __align__(128) char smem[];
    const uint32_t sb = smem_to_u32(smem);
    const int tid = threadIdx.x;
    const int lane = tid & 31;
    const int wid = tid >> 5;
    const int m0 = blockIdx.y * 128;
    const int n0 = blockIdx.x * 128;
    const int wm0 = (wid >> 2) * 64;   // warp m offset in CTA tile
    const int wn0 = (wid & 3) * 32;    // warp n offset

    float acc[4][4][4];
    #pragma unroll
    for (int i = 0; i < 4; i++)
        #pragma unroll
        for (int j = 0; j < 4; j++)
            #pragma unroll
            for (int t = 0; t < 4; t++) acc[i][j][t] = 0.f;

    // ldmatrix per-thread base addresses (stage 0, kstep 0); i/j offsets are
    // immediate constants (i*16*G1_ROWB) so only 2 base registers stay live.
    uint32_t aBase0, bBase0;
    {
        const int seg = lane >> 3;
        const int rA = (lane & 7) + ((seg & 1) << 3);
        const int cA = seg >> 1;
        aBase0 = sb + (uint32_t)(wm0 + rA) * G1_ROWB + cA * 16;
        const int rB = (lane & 7) + ((seg >> 1) << 3);
        const int cB = seg & 1;
        bBase0 = sb + G1_TILEB + (uint32_t)(wn0 + rB) * G1_ROWB + cB * 16;
    }

    // prologue: stages 0,1
    g1_load_stage(sb + 0 * G1_STAGEB, A, g_sfeatT, m0, n0, 0, tid);
    CP_ASYNC_COMMIT();
    g1_load_stage(sb + 1 * G1_STAGEB, A, g_sfeatT, m0, n0, 1, tid);
    CP_ASYNC_COMMIT();

    uint32_t a[2][4][4], b[2][4][2];

    #define G1_LDSM_A(buf, base, ks) do { \
        _Pragma("unroll") \
        for (int _i = 0; _i < 4; _i++) \
            LDSM_X4(a[buf][_i][0], a[buf][_i][1], a[buf][_i][2], a[buf][_i][3], \
                    (base) + _i * (16 * G1_ROWB) + (ks) * 32); \
    } while (0)
    #define G1_LDSM_B(buf, base, ks) do { \
        _Pragma("unroll") \
        for (int _j = 0; _j < 2; _j++) \
            LDSM_X4(b[buf][2*_j][0], b[buf][2*_j][1], b[buf][2*_j+1][0], b[buf][2*_j+1][1], \
                    (base) + _j * (16 * G1_ROWB) + (ks) * 32); \
    } while (0)

    int stage = 0;      // consume stage
    int ns = 2;         // load stage for kt+2
    #pragma unroll 1
    for (int kt = 0; kt < G1_KT; kt++) {
        CP_ASYNC_WAIT_1();
        __syncthreads();

        const int nk = kt + 2;
        if (nk < G1_KT)
            g1_load_stage(sb + ns * G1_STAGEB, A, g_sfeatT, m0, n0, nk, tid);
        CP_ASYNC_COMMIT();

        const uint32_t aAddr = aBase0 + stage * G1_STAGEB;
        const uint32_t bAddr = bBase0 + stage * G1_STAGEB;

        // software-pipelined k-steps: frags for ks+1 load while ks MMAs run
        G1_LDSM_A(0, aAddr, 0);
        G1_LDSM_B(0, bAddr, 0);
        #pragma unroll
        for (int ks = 0; ks < 4; ks++) {
            const int cur = ks & 1, nxt = cur ^ 1;
            if (ks < 3) {
                G1_LDSM_A(nxt, aAddr, ks + 1);
                G1_LDSM_B(nxt, bAddr, ks + 1);
            }
            #pragma unroll
            for (int i = 0; i < 4; i++)
                #pragma unroll
                for (int j = 0; j < 4; j++)
                    MMA_TF32(acc[i][j], a[cur][i], b[cur][j]);
        }

        stage++; if (stage == 3) stage = 0;
        ns++;    if (ns == 3)    ns = 0;
    }
    #undef G1_LDSM_A
    #undef G1_LDSM_B

    // epilogue: agg = dinv_m * acc + dinv_m^2 * feat
    const int r = lane >> 2;
    const int c2 = (lane & 3) * 2;
    #pragma unroll
    for (int i = 0; i < 4; i++) {
        #pragma unroll
        for (int half = 0; half < 2; half++) {
            const int m = m0 + wm0 + i * 16 + r + half * 8;
            const float di = g_dinv[m];
            const float di2 = di * di;
            #pragma unroll
            for (int j = 0; j < 4; j++) {
                const int n = n0 + wn0 + j * 8 + c2;
                float2 fv = *reinterpret_cast<const float2*>(&feat[(size_t)m * F_DIM + n]);
                float2 o;
                o.x = di * acc[i][j][half * 2 + 0] + di2 * fv.x;
                o.y = di * acc[i][j][half * 2 + 1] + di2 * fv.y;
                *reinterpret_cast<float2*>(&g_agg[(size_t)m * F_DIM + n]) = o;
            }
        }
    }
}

// ---------------- kernel 4: out = l2norm_rows(relu(agg @ W)) -----------------
// BM=32 (acc 32/thread -> ~3 CTAs/SM), BN=256 full row, BK=32, 256 threads
// as 8(m) x 32(n), thread tile 4x8. Row ssq via warp shuffle (deterministic).
__global__ void __launch_bounds__(256) gemm2_norm_kernel(const float* __restrict__ W,
                                                         float* __restrict__ out) {
    const int BM = 32, BK = 32, TM = 4, TN = 8;
    __shared__ float As[BK][BM + 1];
    __shared__ float Bs[BK][F_DIM];
    __shared__ float s_ssq[BM];

    const int tid = threadIdx.x;
    const int tn = tid & 31;           // 0..31 -> 256 cols
    const int tm = tid >> 5;           // 0..7  -> 32 rows
    const int m0 = blockIdx.x * BM;

    // A loader: 32x32 = 256 float4, 1/thread
    const int a_r = tid >> 3;          // 0..31
    const int a_c = (tid & 7) * 4;     // 0,4,..28
    // B loader: 32x256 = 2048 float4, 8/thread
    const int b_r0 = tid >> 6;         // 0..3 (stride 4)
    const int b_c  = (tid & 63) * 4;

    float acc[TM][TN] = {};
    float ar[TM], br[TN];

    for (int k0 = 0; k0 < F_DIM; k0 += BK) {
        {
            float4 v = *reinterpret_cast<const float4*>(
                &g_agg[(size_t)(m0 + a_r) * F_DIM + k0 + a_c]);
            As[a_c + 0][a_r] = v.x;
            As[a_c + 1][a_r] = v.y;
            As[a_c + 2][a_r] = v.z;
            As[a_c + 3][a_r] = v.w;
        }
        #pragma unroll
        for (int s = 0; s < 8; s++) {
            int rr = b_r0 + s * 4;
            *reinterpret_cast<float4*>(&Bs[rr][b_c]) =
                *reinterpret_cast<const float4*>(&W[(size_t)(k0 + rr) * F_DIM + b_c]);
        }
        __syncthreads();
        #pragma unroll
        for (int k = 0; k < BK; k++) {
            #pragma unroll
            for (int i = 0; i < TM; i++) ar[i] = As[k][tm * TM + i];
            #pragma unroll
            for (int j = 0; j < TN; j++) br[j] = Bs[k][tn * TN + j];
            #pragma unroll
            for (int i = 0; i < TM; i++)
                #pragma unroll
                for (int j = 0; j < TN; j++)
                    acc[i][j] = fmaf(ar[i], br[j], acc[i][j]);
        }
        __syncthreads();
    }

    // relu + per-row ssq (warp = fixed tm; shuffle-reduce across the 32 tn lanes)
    #pragma unroll
    for (int i = 0; i < TM; i++) {
        float ss = 0.f;
        #pragma unroll
        for (int j = 0; j < TN; j++) {
            float v = fmaxf(acc[i][j], 0.f);
            acc[i][j] = v;
            ss = fmaf(v, v, ss);
        }
        #pragma unroll
        for (int o = 16; o > 0; o >>= 1) ss += __shfl_xor_sync(0xffffffffu, ss, o);
        if (tn == 0) s_ssq[tm * TM + i] = ss;
    }
    __syncthreads();

    #pragma unroll
    for (int i = 0; i < TM; i++) {
        int gi = m0 + tm * TM + i;
        float nrm = sqrtf(s_ssq[tm * TM + i]);
        float sc = 1.0f / fmaxf(nrm, EPS_NORM);
        #pragma unroll
        for (int j = 0; j < TN; j++) {
            int gn = tn * TN + j;
            out[(size_t)gi * F_DIM + gn] = acc[i][j] * sc;
        }
    }
}

// ---------------- host launch -------------------------------------------------
extern "C" void kernel_launch(void* const* d_in, const int* in_sizes, int n_in,
                              void* d_out, int out_size) {
    const float* feat = nullptr;
    const float* A = nullptr;
    const float* W = nullptr;
    for (int i = 0; i < n_in; i++) {
        long long sz = (long long)in_sizes[i];
        if (sz == (long long)N_NODES * N_NODES)      A    = (const float*)d_in[i];
        else if (sz == (long long)N_NODES * F_DIM)   feat = (const float*)d_in[i];
        else if (sz == (long long)F_DIM * F_DIM)     W    = (const float*)d_in[i];
    }
    float* out = (float*)d_out;

    static bool attr_set = false;
    if (!attr_set) {
        cudaFuncSetAttribute(gemm1_mma_kernel,
                             cudaFuncAttributeMaxDynamicSharedMemorySize, G1_SMEM);
        attr_set = true;
    }

    // 1. degrees -> dinv
    rowsum_kernel<<<N_NODES, 256>>>(A);
    // 2. transposed, dinv-scaled, tf32-RN-rounded features (B operand, K-major)
    {
        dim3 grid(N_NODES / 32, F_DIM / 32);
        transpose_scale_kernel<<<grid, dim3(32, 8)>>>(feat);
    }
    // 3. tensor-core GEMM + fused epilogue
    {
        dim3 grid(F_DIM / 128, N_NODES / 128);   // (2, 128) = 256 CTAs, 1 wave @ 2/SM
        gemm1_mma_kernel<<<grid, 256, G1_SMEM>>>(A, feat);
    }
    // 4. projection + relu + row L2 normalize
    gemm2_norm_kernel<<<N_NODES / 32, 256>>>(W, out);
}

// round 9
// speedup vs baseline: 1.5023x; 1.5023x over previous
#include <cuda_runtime.h>
#include <cuda_fp16.h>
#include <math.h>
#include <stdint.h>

#define N_NODES 16384
#define F_DIM   256
#define EPS_NORM 1e-12f

// ---------------- scratch (allocation-free: __device__ globals) ----------------
__device__ float  g_dinv[N_NODES];                   // 1/sqrt(deg)
__device__ __half g_Ah[(size_t)N_NODES * N_NODES];   // fp16(A), row-major (512 MB)
__device__ __half g_sfeatT[F_DIM * N_NODES];         // fp16(dinv[k]*feat[k][n]), [n][k]
__device__ float  g_agg[N_NODES * F_DIM];            // feat_agg

// ============================ PTX helpers (sm_80+ portable) ==================
__device__ __forceinline__ uint32_t smem_to_u32(const void* p) {
    uint32_t a;
    asm("{ .reg .u64 t; cvta.to.shared.u64 t, %1; cvt.u32.u64 %0, t; }" : "=r"(a) : "l"(p));
    return a;
}

__device__ __forceinline__ uint32_t h2_bits(__half2 h) {
    return *reinterpret_cast<uint32_t*>(&h);
}

#define LDSM_X4(r0, r1, r2, r3, addr) \
    asm volatile("ldmatrix.sync.aligned.m8n8.x4.shared.b16 {%0,%1,%2,%3}, [%4];" \
        : "=r"(r0), "=r"(r1), "=r"(r2), "=r"(r3) : "r"(addr))

// fp16 MMA, fp32 accumulate: a=4 regs, b=2 regs
#define MMA_F16(d, a, b) \
    asm volatile("mma.sync.aligned.m16n8k16.row.col.f32.f16.f16.f32 " \
        "{%0,%1,%2,%3}, {%4,%5,%6,%7}, {%8,%9}, {%0,%1,%2,%3};" \
        : "+f"((d)[0]), "+f"((d)[1]), "+f"((d)[2]), "+f"((d)[3]) \
        : "r"((a)[0]), "r"((a)[1]), "r"((a)[2]), "r"((a)[3]), \
          "r"((b)[0]), "r"((b)[1]))

#define CP_ASYNC_16(dst, src) \
    asm volatile("cp.async.cg.shared.global [%0], [%1], 16;" :: "r"(dst), "l"(src))
#define CP_ASYNC_COMMIT() asm volatile("cp.async.commit_group;" ::: "memory")
#define CP_ASYNC_WAIT_1() asm volatile("cp.async.wait_group 1;" ::: "memory")

// ---------------- kernel 1: rowsum + fp16 convert of A -----------------------
// One block per row: d = sum(A_row)+1 -> dinv; also writes g_Ah = fp16(A_row).
__global__ void __launch_bounds__(256) rowsum_convert_kernel(const float* __restrict__ A) {
    const int row = blockIdx.x;
    const float4* arow = reinterpret_cast<const float4*>(A + (size_t)row * N_NODES);
    uint4* hrow = reinterpret_cast<uint4*>(g_Ah + (size_t)row * N_NODES);
    const int t = threadIdx.x;
    float s = 0.f;
    #pragma unroll
    for (int j = 0; j < 8; j++) {
        // thread t handles float4 pair (2t, 2t+1) within each 2048-float slab
        int f4 = j * 512 + t * 2;
        float4 v0 = arow[f4];
        float4 v1 = arow[f4 + 1];
        s += ((v0.x + v0.y) + (v0.z + v0.w)) + ((v1.x + v1.y) + (v1.z + v1.w));
        uint4 o;
        o.x = h2_bits(__floats2half2_rn(v0.x, v0.y));
        o.y = h2_bits(__floats2half2_rn(v0.z, v0.w));
        o.z = h2_bits(__floats2half2_rn(v1.x, v1.y));
        o.w = h2_bits(__floats2half2_rn(v1.z, v1.w));
        hrow[j * 256 + t] = o;
    }
    __shared__ float red[8];
    #pragma unroll
    for (int o = 16; o > 0; o >>= 1) s += __shfl_down_sync(0xffffffffu, s, o);
    if ((t & 31) == 0) red[t >> 5] = s;
    __syncthreads();
    if (t < 32) {
        s = (t < 8) ? red[t] : 0.f;
        #pragma unroll
        for (int o = 4; o > 0; o >>= 1) s += __shfl_down_sync(0xffffffffu, s, o);
        if (t == 0) g_dinv[row] = rsqrtf(s + 1.0f);
    }
}

// ---------------- kernel 2: sfeatT[n][k] = fp16(dinv[k] * feat[k][n]) --------
__global__ void __launch_bounds__(256) transpose_scale_kernel(const float* __restrict__ feat) {
    __shared__ float tbuf[32][33];
    const int k0 = blockIdx.x * 32;
    const int n0 = blockIdx.y * 32;
    const int tx = threadIdx.x, ty = threadIdx.y;
    #pragma unroll
    for (int i = 0; i < 4; i++) {
        int k = k0 + ty + i * 8;
        tbuf[ty + i * 8][tx] = g_dinv[k] * feat[(size_t)k * F_DIM + n0 + tx];
    }
    __syncthreads();
    #pragma unroll
    for (int i = 0; i < 4; i++) {
        int n = n0 + ty + i * 8;
        g_sfeatT[(size_t)n * N_NODES + k0 + tx] = __float2half_rn(tbuf[tx][ty + i * 8]);
    }
}

// ---------------- kernel 3: GEMM1 via mma.sync fp16 --------------------------
// C[16384,256] = Ah @ sfeatT^T (fp32 acc); agg = dinv_i*C + dinv_i^2*feat
// CTA tile 128x128x64 (fp16), 3-stage cp.async, 8 warps (2m x 4n), warp 64x32.
#define G1_BK       64                          /* k per stage (halves) */
#define G1_KT       (N_NODES / G1_BK)           /* 256 */
#define G1_ROWB     144                         /* 64 halves (128B) + 16B pad */
#define G1_TILEB    (128 * G1_ROWB)             /* 18432 per operand tile */
#define G1_STAGEB   (2 * G1_TILEB)              /* 36864 */
#define G1_SMEM     (3 * G1_STAGEB)             /* 110592 */

__device__ __forceinline__ void g1_load_stage(uint32_t sbuf,
                                              const __half* __restrict__ Ah,
                                              const __half* __restrict__ BT,
                                              int m0, int n0, int kt, int tid) {
    const int k0 = kt * G1_BK;
    // each operand: 128 rows x 128 B = 1024 x 16B chunks, 4 per thread
    #pragma unroll
    for (int i = 0; i < 4; i++) {
        int id = tid + i * 256;
        int row = id >> 3, c = id & 7;          // c*16B = c*8 halves
        uint32_t dst = sbuf + row * G1_ROWB + c * 16;
        const __half* src = Ah + (size_t)(m0 + row) * N_NODES + k0 + c * 8;
        CP_ASYNC_16(dst, src);
    }
    #pragma unroll
    for (int i = 0; i < 4; i++) {
        int id = tid + i * 256;
        int row = id >> 3, c = id & 7;
        uint32_t dst = sbuf + G1_TILEB + row * G1_ROWB + c * 16;
        const __half* src = BT + (size_t)(n0 + row) * N_NODES + k0 + c * 8;
        CP_ASYNC_16(dst, src);
    }
}

__global__ void __launch_bounds__(256, 2) gemm1_mma_kernel(const float* __restrict__ feat) {
    extern __shared__ __align__(128) char smem[];
    const uint32_t sb = smem_to_u32(smem);
    const int tid = threadIdx.x;
    const int lane = tid & 31;
    const int wid = tid >> 5;
    const int m0 = blockIdx.y * 128;
    const int n0 = blockIdx.x * 128;
    const int wm0 = (wid >> 2) * 64;   // warp m offset
    const int wn0 = (wid & 3) * 32;    // warp n offset

    float acc[4][4][4];
    #pragma unroll
    for (int i = 0; i < 4; i++)
        #pragma unroll
        for (int j = 0; j < 4; j++)
            #pragma unroll
            for (int t = 0; t < 4; t++) acc[i][j][t] = 0.f;

    // ldmatrix base addrs (stage 0, kstep 0).
    // A x4: (m0-7,k0-7)(m8-15,k0-7)(m0-7,k8-15)(m8-15,k8-15) = a0..a3 of m16n8k16
    // B x4: two n-blocks x (kLo,kHi) -> {b0,b1} pairs
    uint32_t aBase0, bBase0;
    {
        const int seg = lane >> 3;
        const int rA = (lane & 7) + ((seg & 1) << 3);
        const int cA = seg >> 1;                 // k-half selector, 16B each
        aBase0 = sb + (uint32_t)(wm0 + rA) * G1_ROWB + cA * 16;
        const int rB = (lane & 7) + ((seg >> 1) << 3);
        const int cB = seg & 1;
        bBase0 = sb + G1_TILEB + (uint32_t)(wn0 + rB) * G1_ROWB + cB * 16;
    }

    g1_load_stage(sb + 0 * G1_STAGEB, g_Ah, g_sfeatT, m0, n0, 0, tid);
    CP_ASYNC_COMMIT();
    g1_load_stage(sb + 1 * G1_STAGEB, g_Ah, g_sfeatT, m0, n0, 1, tid);
    CP_ASYNC_COMMIT();

    int stage = 0;
    int ns = 2;
    #pragma unroll 1
    for (int kt = 0; kt < G1_KT; kt++) {
        CP_ASYNC_WAIT_1();
        __syncthreads();

        const int nk = kt + 2;
        if (nk < G1_KT)
            g1_load_stage(sb + ns * G1_STAGEB, g_Ah, g_sfeatT, m0, n0, nk, tid);
        CP_ASYNC_COMMIT();

        const uint32_t aAddr = aBase0 + stage * G1_STAGEB;
        const uint32_t bAddr = bBase0 + stage * G1_STAGEB;

        #pragma unroll
        for (int ks = 0; ks < 4; ks++) {         // 4 k16-steps per kt(64)
            uint32_t a[4][4], b[4][2];
            #pragma unroll
            for (int i = 0; i < 4; i++)
                LDSM_X4(a[i][0], a[i][1], a[i][2], a[i][3],
                        aAddr + i * (16 * G1_ROWB) + ks * 32);
            #pragma unroll
            for (int j = 0; j < 2; j++)
                LDSM_X4(b[2 * j][0], b[2 * j][1], b[2 * j + 1][0], b[2 * j + 1][1],
                        bAddr + j * (16 * G1_ROWB) + ks * 32);
            #pragma unroll
            for (int i = 0; i < 4; i++)
                #pragma unroll
                for (int j = 0; j < 4; j++)
                    MMA_F16(acc[i][j], a[i], b[j]);
        }

        stage++; if (stage == 3) stage = 0;
        ns++;    if (ns == 3)    ns = 0;
    }

    // epilogue: agg = dinv_m * acc + dinv_m^2 * feat   (identity term exact, fp32)
    const int r = lane >> 2;
    const int c2 = (lane & 3) * 2;
    #pragma unroll
    for (int i = 0; i < 4; i++) {
        #pragma unroll
        for (int half = 0; half < 2; half++) {
            const int m = m0 + wm0 + i * 16 + r + half * 8;
            const float di = g_dinv[m];
            const float di2 = di * di;
            #pragma unroll
            for (int j = 0; j < 4; j++) {
                const int n = n0 + wn0 + j * 8 + c2;
                float2 fv = *reinterpret_cast<const float2*>(&feat[(size_t)m * F_DIM + n]);
                float2 o;
                o.x = di * acc[i][j][half * 2 + 0] + di2 * fv.x;
                o.y = di * acc[i][j][half * 2 + 1] + di2 * fv.y;
                *reinterpret_cast<float2*>(&g_agg[(size_t)m * F_DIM + n]) = o;
            }
        }
    }
}

// ---------------- kernel 4: out = l2norm_rows(relu(agg @ W)) -----------------
// (R5 version: BM=64, BN=256, BK=16 — measured 82us)
__global__ void __launch_bounds__(256) gemm2_norm_kernel(const float* __restrict__ W,
                                                         float* __restrict__ out) {
    const int BM = 64, BK = 16, TM = 8, TN = 8;
    __shared__ float As[BK][BM + 1];
    __shared__ float Bs[BK][F_DIM];
    __shared__ float s_ssq[BM];

    const int tid = threadIdx.x;
    const int tn = tid & 31;
    const int tm = tid >> 5;
    const int m0 = blockIdx.x * BM;

    if (tid < BM) s_ssq[tid] = 0.f;

    const int a_r = tid >> 2;
    const int a_c = (tid & 3) * 4;
    const int b_r = tid >> 6;
    const int b_c = (tid & 63) * 4;

    float acc[TM][TN] = {};
    float ar[TM], br[TN];

    for (int k0 = 0; k0 < F_DIM; k0 += BK) {
        {
            float4 v = *reinterpret_cast<const float4*>(
                &g_agg[(size_t)(m0 + a_r) * F_DIM + k0 + a_c]);
            As[a_c + 0][a_r] = v.x;
            As[a_c + 1][a_r] = v.y;
            As[a_c + 2][a_r] = v.z;
            As[a_c + 3][a_r] = v.w;
        }
        #pragma unroll
        for (int s = 0; s < 4; s++) {
            int rr = b_r + s * 4;
            *reinterpret_cast<float4*>(&Bs[rr][b_c]) =
                *reinterpret_cast<const float4*>(&W[(size_t)(k0 + rr) * F_DIM + b_c]);
        }
        __syncthreads();
        #pragma unroll
        for (int k = 0; k < BK; k++) {
            #pragma unroll
            for (int i = 0; i < TM; i++) ar[i] = As[k][tm * TM + i];
            #pragma unroll
            for (int j = 0; j < TN; j++) br[j] = Bs[k][tn * TN + j];
            #pragma unroll
            for (int i = 0; i < TM; i++)
                #pragma unroll
                for (int j = 0; j < TN; j++)
                    acc[i][j] = fmaf(ar[i], br[j], acc[i][j]);
        }
        __syncthreads();
    }

    #pragma unroll
    for (int i = 0; i < TM; i++) {
        float ss = 0.f;
        #pragma unroll
        for (int j = 0; j < TN; j++) {
            float v = fmaxf(acc[i][j], 0.f);
            acc[i][j] = v;
            ss = fmaf(v, v, ss);
        }
        atomicAdd(&s_ssq[tm * TM + i], ss);
    }
    __syncthreads();

    #pragma unroll
    for (int i = 0; i < TM; i++) {
        int gi = m0 + tm * TM + i;
        float nrm = sqrtf(s_ssq[tm * TM + i]);
        float sc = 1.0f / fmaxf(nrm, EPS_NORM);
        #pragma unroll
        for (int j = 0; j < TN; j++) {
            int gn = tn * TN + j;
            out[(size_t)gi * F_DIM + gn] = acc[i][j] * sc;
        }
    }
}

// ---------------- host launch -------------------------------------------------
extern "C" void kernel_launch(void* const* d_in, const int* in_sizes, int n_in,
                              void* d_out, int out_size) {
    const float* feat = nullptr;
    const float* A = nullptr;
    const float* W = nullptr;
    for (int i = 0; i < n_in; i++) {
        long long sz = (long long)in_sizes[i];
        if (sz == (long long)N_NODES * N_NODES)      A    = (const float*)d_in[i];
        else if (sz == (long long)N_NODES * F_DIM)   feat = (const float*)d_in[i];
        else if (sz == (long long)F_DIM * F_DIM)     W    = (const float*)d_in[i];
    }
    float* out = (float*)d_out;

    static bool attr_set = false;
    if (!attr_set) {
        cudaFuncSetAttribute(gemm1_mma_kernel,
                             cudaFuncAttributeMaxDynamicSharedMemorySize, G1_SMEM);
        attr_set = true;
    }

    // 1. degrees -> dinv, plus A -> fp16 copy
    rowsum_convert_kernel<<<N_NODES, 256>>>(A);
    // 2. transposed, dinv-scaled fp16 features (B operand, K-major)
    {
        dim3 grid(N_NODES / 32, F_DIM / 32);
        transpose_scale_kernel<<<grid, dim3(32, 8)>>>(feat);
    }
    // 3. fp16 tensor-core GEMM + fused epilogue
    {
        dim3 grid(F_DIM / 128, N_NODES / 128);   // (2, 128) = 256 CTAs, 2/SM, 1 wave
        gemm1_mma_kernel<<<grid, 256, G1_SMEM>>>(feat);
    }
    // 4. projection + relu + row L2 normalize
    gemm2_norm_kernel<<<N_NODES / 64, 256>>>(W, out);
}